// round 11
// baseline (speedup 1.0000x reference)
#include <cuda_runtime.h>
#include <math.h>

// Problem constants (from reference: x [65536, 512], W [512, 512], fp32)
#define BATCH   65536
#define DIM     512
#define N_ITERS 50

// GEMM tiling
#define BM 128
#define BN 128
#define BK 16
#define TM 8
#define TN 8
#define NTHREADS 256

// Ping-pong scratch (allowed: __device__ global array, no runtime alloc)
__device__ float g_scratch[(size_t)BATCH * DIM];

// ---------------------------------------------------------------------------
// Iteration 1: z1 = tanh(0 @ W^T + x) = tanh(x)   (pure elementwise)
// ---------------------------------------------------------------------------
__global__ void tanh_init_kernel(const float* __restrict__ x,
                                 float* __restrict__ out) {
    size_t i = (size_t)blockIdx.x * blockDim.x + threadIdx.x;
    size_t stride = (size_t)gridDim.x * blockDim.x;
    size_t n4 = ((size_t)BATCH * DIM) / 4;
    const float4* x4 = reinterpret_cast<const float4*>(x);
    float4* o4 = reinterpret_cast<float4*>(out);
    for (; i < n4; i += stride) {
        float4 v = x4[i];
        float4 r;
        r.x = tanhf(v.x);
        r.y = tanhf(v.y);
        r.z = tanhf(v.z);
        r.w = tanhf(v.w);
        o4[i] = r;
    }
}

// ---------------------------------------------------------------------------
// Fused iteration: Out[b,d] = tanh( sum_k Z[b,k] * W[d,k] + X[b,d] )
// NT GEMM: Z [BATCH x DIM] row-major, W [DIM x DIM] row-major (K contiguous
// in both), fused bias-add (X) + tanh epilogue.
// Tile: 128x128x16, 256 threads, 8x8 accumulator per thread.
// ---------------------------------------------------------------------------
__global__ void __launch_bounds__(NTHREADS)
fused_gemm_tanh_kernel(const float* __restrict__ Z,
                       const float* __restrict__ W,
                       const float* __restrict__ X,
                       float* __restrict__ Out) {
    __shared__ float As[BK][BM];   // A^T tile: As[k][m]
    __shared__ float Bs[BK][BN];   // B^T tile: Bs[k][n]

    const int block_m = blockIdx.y * BM;   // row tile of Z / Out
    const int block_n = blockIdx.x * BN;   // row tile of W == col tile of Out
    const int tid = threadIdx.x;
    const int tx = tid & 15;               // n direction (0..15)
    const int ty = tid >> 4;               // m direction (0..15)

    float acc[TM][TN];
#pragma unroll
    for (int i = 0; i < TM; i++)
#pragma unroll
        for (int j = 0; j < TN; j++) acc[i][j] = 0.0f;

    // Tile-load mapping: 2048 floats = 512 float4 per tile; 2 float4/thread.
    // f -> (row = f>>2, 4-col group = (f&3)*4)
    const int f0_row = tid >> 2;
    const int f0_c4 = (tid & 3) * 4;
    const int f1_row = (tid + 256) >> 2;
    const int f1_c4 = f0_c4;  // (tid+256)&3 == tid&3

    const float* Zrow0 = Z + (size_t)(block_m + f0_row) * DIM;
    const float* Zrow1 = Z + (size_t)(block_m + f1_row) * DIM;
    const float* Wrow0 = W + (size_t)(block_n + f0_row) * DIM;
    const float* Wrow1 = W + (size_t)(block_n + f1_row) * DIM;

    for (int k0 = 0; k0 < DIM; k0 += BK) {
        // --- load A (Z) tile, transposed into As[k][m] ---
        {
            float4 v = *reinterpret_cast<const float4*>(Zrow0 + k0 + f0_c4);
            As[f0_c4 + 0][f0_row] = v.x;
            As[f0_c4 + 1][f0_row] = v.y;
            As[f0_c4 + 2][f0_row] = v.z;
            As[f0_c4 + 3][f0_row] = v.w;
            float4 u = *reinterpret_cast<const float4*>(Zrow1 + k0 + f1_c4);
            As[f1_c4 + 0][f1_row] = u.x;
            As[f1_c4 + 1][f1_row] = u.y;
            As[f1_c4 + 2][f1_row] = u.z;
            As[f1_c4 + 3][f1_row] = u.w;
        }
        // --- load B (W) tile, transposed into Bs[k][n] ---
        {
            float4 v = *reinterpret_cast<const float4*>(Wrow0 + k0 + f0_c4);
            Bs[f0_c4 + 0][f0_row] = v.x;
            Bs[f0_c4 + 1][f0_row] = v.y;
            Bs[f0_c4 + 2][f0_row] = v.z;
            Bs[f0_c4 + 3][f0_row] = v.w;
            float4 u = *reinterpret_cast<const float4*>(Wrow1 + k0 + f1_c4);
            Bs[f1_c4 + 0][f1_row] = u.x;
            Bs[f1_c4 + 1][f1_row] = u.y;
            Bs[f1_c4 + 2][f1_row] = u.z;
            Bs[f1_c4 + 3][f1_row] = u.w;
        }
        __syncthreads();

#pragma unroll
        for (int k = 0; k < BK; k++) {
            float a[TM], b[TN];
            *reinterpret_cast<float4*>(&a[0]) =
                *reinterpret_cast<const float4*>(&As[k][ty * TM]);
            *reinterpret_cast<float4*>(&a[4]) =
                *reinterpret_cast<const float4*>(&As[k][ty * TM + 4]);
            *reinterpret_cast<float4*>(&b[0]) =
                *reinterpret_cast<const float4*>(&Bs[k][tx * TN]);
            *reinterpret_cast<float4*>(&b[4]) =
                *reinterpret_cast<const float4*>(&Bs[k][tx * TN + 4]);
#pragma unroll
            for (int i = 0; i < TM; i++)
#pragma unroll
                for (int j = 0; j < TN; j++) acc[i][j] += a[i] * b[j];
        }
        __syncthreads();
    }

    // --- epilogue: += X, tanh, store ---
#pragma unroll
    for (int i = 0; i < TM; i++) {
        const int gm = block_m + ty * TM + i;
        const int gn = block_n + tx * TN;
        const float4* xr =
            reinterpret_cast<const float4*>(X + (size_t)gm * DIM + gn);
        float4* orow = reinterpret_cast<float4*>(Out + (size_t)gm * DIM + gn);
        float4 x0 = xr[0];
        float4 x1 = xr[1];
        float4 r0, r1;
        r0.x = tanhf(acc[i][0] + x0.x);
        r0.y = tanhf(acc[i][1] + x0.y);
        r0.z = tanhf(acc[i][2] + x0.z);
        r0.w = tanhf(acc[i][3] + x0.w);
        r1.x = tanhf(acc[i][4] + x1.x);
        r1.y = tanhf(acc[i][5] + x1.y);
        r1.z = tanhf(acc[i][6] + x1.z);
        r1.w = tanhf(acc[i][7] + x1.w);
        orow[0] = r0;
        orow[1] = r1;
    }
}

// ---------------------------------------------------------------------------
// Launch: iter 1 = tanh(x) -> scratch; iters 2..50 ping-pong scratch <-> d_out.
// 49 GEMM iterations; even-numbered iterations land in d_out, so iter 50
// (even) writes the final result to d_out. All plain kernel launches:
// graph-capturable, no allocation, no sync.
// ---------------------------------------------------------------------------
extern "C" void kernel_launch(void* const* d_in, const int* in_sizes, int n_in,
                              void* d_out, int out_size) {
    const float* x = (const float*)d_in[0];   // [BATCH, DIM]
    const float* W = (const float*)d_in[1];   // [DIM, DIM]
    float* out = (float*)d_out;               // [BATCH, DIM]

    float* scratch = nullptr;
    cudaGetSymbolAddress((void**)&scratch, g_scratch);

    // Iteration 1: z1 = tanh(x)
    {
        int threads = 256;
        int blocks = 1024;
        tanh_init_kernel<<<blocks, threads>>>(x, scratch);
    }

    // Iterations 2..50
    dim3 grid(DIM / BN, BATCH / BM);  // (4, 512)
    for (int it = 2; it <= N_ITERS; it++) {
        const float* src = (it % 2 == 0) ? scratch : out;
        float* dst = (it % 2 == 0) ? out : scratch;
        fused_gemm_tanh_kernel<<<grid, NTHREADS>>>(src, W, x, dst);
    }
}

// round 15
// speedup vs baseline: 1.0006x; 1.0006x over previous
#include <cuda_runtime.h>
#include <math.h>

// Problem constants (from reference: x [65536, 512], W [512, 512], fp32)
#define BATCH   65536
#define DIM     512
#define N_ITERS 50

// GEMM tiling
#define BM 128
#define BN 128
#define BK 16
#define TM 8
#define TN 8
#define NTHREADS 256

// Ping-pong scratch (allowed: __device__ global array, no runtime alloc)
__device__ float g_scratch[(size_t)BATCH * DIM];

// ---------------------------------------------------------------------------
// Iteration 1: z1 = tanh(0 @ W^T + x) = tanh(x)   (pure elementwise)
// ---------------------------------------------------------------------------
__global__ void tanh_init_kernel(const float* __restrict__ x,
                                 float* __restrict__ out) {
    size_t i = (size_t)blockIdx.x * blockDim.x + threadIdx.x;
    size_t stride = (size_t)gridDim.x * blockDim.x;
    size_t n4 = ((size_t)BATCH * DIM) / 4;
    const float4* x4 = reinterpret_cast<const float4*>(x);
    float4* o4 = reinterpret_cast<float4*>(out);
    for (; i < n4; i += stride) {
        float4 v = x4[i];
        float4 r;
        r.x = tanhf(v.x);
        r.y = tanhf(v.y);
        r.z = tanhf(v.z);
        r.w = tanhf(v.w);
        o4[i] = r;
    }
}

// ---------------------------------------------------------------------------
// Fused iteration: Out[b,d] = tanh( sum_k Z[b,k] * W[d,k] + X[b,d] )
// NT GEMM: Z [BATCH x DIM] row-major, W [DIM x DIM] row-major (K contiguous
// in both), fused bias-add (X) + tanh epilogue.
// Tile: 128x128x16, 256 threads, 8x8 accumulator per thread.
// ---------------------------------------------------------------------------
__global__ void __launch_bounds__(NTHREADS)
fused_gemm_tanh_kernel(const float* __restrict__ Z,
                       const float* __restrict__ W,
                       const float* __restrict__ X,
                       float* __restrict__ Out) {
    __shared__ float As[BK][BM];   // A^T tile: As[k][m]
    __shared__ float Bs[BK][BN];   // B^T tile: Bs[k][n]

    const int block_m = blockIdx.y * BM;   // row tile of Z / Out
    const int block_n = blockIdx.x * BN;   // row tile of W == col tile of Out
    const int tid = threadIdx.x;
    const int tx = tid & 15;               // n direction (0..15)
    const int ty = tid >> 4;               // m direction (0..15)

    float acc[TM][TN];
#pragma unroll
    for (int i = 0; i < TM; i++)
#pragma unroll
        for (int j = 0; j < TN; j++) acc[i][j] = 0.0f;

    // Tile-load mapping: 2048 floats = 512 float4 per tile; 2 float4/thread.
    // f -> (row = f>>2, 4-col group = (f&3)*4)
    const int f0_row = tid >> 2;
    const int f0_c4 = (tid & 3) * 4;
    const int f1_row = (tid + 256) >> 2;
    const int f1_c4 = f0_c4;  // (tid+256)&3 == tid&3

    const float* Zrow0 = Z + (size_t)(block_m + f0_row) * DIM;
    const float* Zrow1 = Z + (size_t)(block_m + f1_row) * DIM;
    const float* Wrow0 = W + (size_t)(block_n + f0_row) * DIM;
    const float* Wrow1 = W + (size_t)(block_n + f1_row) * DIM;

    for (int k0 = 0; k0 < DIM; k0 += BK) {
        // --- load A (Z) tile, transposed into As[k][m] ---
        {
            float4 v = *reinterpret_cast<const float4*>(Zrow0 + k0 + f0_c4);
            As[f0_c4 + 0][f0_row] = v.x;
            As[f0_c4 + 1][f0_row] = v.y;
            As[f0_c4 + 2][f0_row] = v.z;
            As[f0_c4 + 3][f0_row] = v.w;
            float4 u = *reinterpret_cast<const float4*>(Zrow1 + k0 + f1_c4);
            As[f1_c4 + 0][f1_row] = u.x;
            As[f1_c4 + 1][f1_row] = u.y;
            As[f1_c4 + 2][f1_row] = u.z;
            As[f1_c4 + 3][f1_row] = u.w;
        }
        // --- load B (W) tile, transposed into Bs[k][n] ---
        {
            float4 v = *reinterpret_cast<const float4*>(Wrow0 + k0 + f0_c4);
            Bs[f0_c4 + 0][f0_row] = v.x;
            Bs[f0_c4 + 1][f0_row] = v.y;
            Bs[f0_c4 + 2][f0_row] = v.z;
            Bs[f0_c4 + 3][f0_row] = v.w;
            float4 u = *reinterpret_cast<const float4*>(Wrow1 + k0 + f1_c4);
            Bs[f1_c4 + 0][f1_row] = u.x;
            Bs[f1_c4 + 1][f1_row] = u.y;
            Bs[f1_c4 + 2][f1_row] = u.z;
            Bs[f1_c4 + 3][f1_row] = u.w;
        }
        __syncthreads();

#pragma unroll
        for (int k = 0; k < BK; k++) {
            float a[TM], b[TN];
            *reinterpret_cast<float4*>(&a[0]) =
                *reinterpret_cast<const float4*>(&As[k][ty * TM]);
            *reinterpret_cast<float4*>(&a[4]) =
                *reinterpret_cast<const float4*>(&As[k][ty * TM + 4]);
            *reinterpret_cast<float4*>(&b[0]) =
                *reinterpret_cast<const float4*>(&Bs[k][tx * TN]);
            *reinterpret_cast<float4*>(&b[4]) =
                *reinterpret_cast<const float4*>(&Bs[k][tx * TN + 4]);
#pragma unroll
            for (int i = 0; i < TM; i++)
#pragma unroll
                for (int j = 0; j < TN; j++) acc[i][j] += a[i] * b[j];
        }
        __syncthreads();
    }

    // --- epilogue: += X, tanh, store ---
#pragma unroll
    for (int i = 0; i < TM; i++) {
        const int gm = block_m + ty * TM + i;
        const int gn = block_n + tx * TN;
        const float4* xr =
            reinterpret_cast<const float4*>(X + (size_t)gm * DIM + gn);
        float4* orow = reinterpret_cast<float4*>(Out + (size_t)gm * DIM + gn);
        float4 x0 = xr[0];
        float4 x1 = xr[1];
        float4 r0, r1;
        r0.x = tanhf(acc[i][0] + x0.x);
        r0.y = tanhf(acc[i][1] + x0.y);
        r0.z = tanhf(acc[i][2] + x0.z);
        r0.w = tanhf(acc[i][3] + x0.w);
        r1.x = tanhf(acc[i][4] + x1.x);
        r1.y = tanhf(acc[i][5] + x1.y);
        r1.z = tanhf(acc[i][6] + x1.z);
        r1.w = tanhf(acc[i][7] + x1.w);
        orow[0] = r0;
        orow[1] = r1;
    }
}

// ---------------------------------------------------------------------------
// Launch: iter 1 = tanh(x) -> scratch; iters 2..50 ping-pong scratch <-> d_out.
// 49 GEMM iterations; even-numbered iterations land in d_out, so iter 50
// (even) writes the final result to d_out. All plain kernel launches:
// graph-capturable, no allocation, no sync.
// ---------------------------------------------------------------------------
extern "C" void kernel_launch(void* const* d_in, const int* in_sizes, int n_in,
                              void* d_out, int out_size) {
    const float* x = (const float*)d_in[0];   // [BATCH, DIM]
    const float* W = (const float*)d_in[1];   // [DIM, DIM]
    float* out = (float*)d_out;               // [BATCH, DIM]

    float* scratch = nullptr;
    cudaGetSymbolAddress((void**)&scratch, g_scratch);

    // Iteration 1: z1 = tanh(x)
    {
        int threads = 256;
        int blocks = 1024;
        tanh_init_kernel<<<blocks, threads>>>(x, scratch);
    }

    // Iterations 2..50
    dim3 grid(DIM / BN, BATCH / BM);  // (4, 512)
    for (int it = 2; it <= N_ITERS; it++) {
        const float* src = (it % 2 == 0) ? scratch : out;
        float* dst = (it % 2 == 0) ? out : scratch;
        fused_gemm_tanh_kernel<<<grid, NTHREADS>>>(src, W, x, dst);
    }
}